// round 3
// baseline (speedup 1.0000x reference)
#include <cuda_runtime.h>
#include <math_constants.h>

#define NN 100000
#define FI 256
#define FH 128
#define FO 40

typedef unsigned long long u64;

// ---------------- scratch (static device globals) ---------------------------
__device__ __align__(256) float g_deg[NN];
__device__ __align__(256) float g_dinv[NN];
__device__ __align__(256) float g_h1[NN * FH];    // x @ W1
__device__ __align__(256) float g_agg1[NN * FH];  // b1 + self + edge aggregate
__device__ __align__(256) float g_h2[NN * FO];    // relu(agg1) @ W2
__device__ __align__(256) float g_agg2[NN * FO];  // b2 + self + edge aggregate
__device__ int g_is64;

// ---------------- packed fp32x2 helpers -------------------------------------
__device__ __forceinline__ u64 pack2(float lo, float hi) {
    u64 r; asm("mov.b64 %0, {%1, %2};" : "=l"(r) : "f"(lo), "f"(hi)); return r;
}
__device__ __forceinline__ float2 unpack2(u64 v) {
    float2 f; asm("mov.b64 {%0, %1}, %2;" : "=f"(f.x), "=f"(f.y) : "l"(v)); return f;
}
__device__ __forceinline__ u64 ffma2(u64 a, u64 b, u64 c) {
    u64 d; asm("fma.rn.f32x2 %0, %1, %2, %3;" : "=l"(d) : "l"(a), "l"(b), "l"(c)); return d;
}
__device__ __forceinline__ void red_add_v4(float* p, float a, float b, float c, float d) {
    asm volatile("red.global.add.v4.f32 [%0], {%1,%2,%3,%4};"
                 :: "l"(p), "f"(a), "f"(b), "f"(c), "f"(d) : "memory");
}
__device__ __forceinline__ int eidx(const void* p, long long i, int is64) {
    if (is64) return (int)((const long long*)p)[i];
    return ((const int*)p)[i];
}

// ---------------- dtype probe ------------------------------------------------
__global__ void k_detect(const void* ei) {
    if (blockIdx.x == 0 && threadIdx.x == 0) {
        const long long* p = (const long long*)ei;
        int ok = 1;
        #pragma unroll
        for (int i = 0; i < 32; i++) {
            long long v = p[i];
            if (v < 0 || v >= NN) ok = 0;
        }
        g_is64 = ok;
    }
}

// ---------------- degree / normalization ------------------------------------
__global__ void k_deg_init() {
    int i = blockIdx.x * blockDim.x + threadIdx.x;
    if (i < NN) g_deg[i] = 1.0f;
}
__global__ void k_deg_count(const void* ei, int E) {
    int i = blockIdx.x * blockDim.x + threadIdx.x;
    if (i < E) {
        int d = eidx(ei, (long long)E + i, g_is64);
        atomicAdd(&g_deg[d], 1.0f);
    }
}
__global__ void k_dinv() {
    int i = blockIdx.x * blockDim.x + threadIdx.x;
    if (i < NN) g_dinv[i] = rsqrtf(fmaxf(g_deg[i], 1.0f));
}

// ---------------- GEMM1: 100000x256 @ 256x128, packed f32x2 -----------------
// 256 thr: tx=t&31 -> colpairs {tx, tx+32}; tg=t>>5 -> rows tg*4..+3. 32 rows/blk.
// Epilogue fuses: h1 = acc ; agg1 = b1 + acc*dinv^2 (self-loop init).
__global__ void __launch_bounds__(256) k_gemm1(const float* __restrict__ x,
                                               const float* __restrict__ W1,
                                               const float* __restrict__ b1) {
    __shared__ u64 Ws2[64 * 64];  // [(k>>2)*64 + cp]*4 + (k&3)   (32 KB)
    __shared__ u64 Xs2[32 * 64];  // [row][k], value duplicated   (16 KB)
    int t = threadIdx.x;
    int tx = t & 31, tg = t >> 5;
    int row0 = blockIdx.x * 32;

    u64 acc[2][4];
    #pragma unroll
    for (int c = 0; c < 2; c++)
        #pragma unroll
        for (int r = 0; r < 4; r++) acc[c][r] = 0ULL;

    for (int kt = 0; kt < 4; kt++) {
        const float2* Wg = (const float2*)(W1 + (size_t)(kt * 64) * 128);
        for (int i = t; i < 4096; i += 256) {
            int k = i >> 6, cp = i & 63;
            float2 w = Wg[i];
            Ws2[(((k >> 2) * 64) + cp) * 4 + (k & 3)] = pack2(w.x, w.y);
        }
        for (int i = t; i < 2048; i += 256) {
            int r = i >> 6, k = i & 63;
            float v = x[(size_t)(row0 + r) * FI + kt * 64 + k];
            Xs2[i] = pack2(v, v);
        }
        __syncthreads();

        #pragma unroll
        for (int k = 0; k < 64; k += 4) {
            const ulonglong2* wp0 = (const ulonglong2*)&Ws2[(((k >> 2) * 64) + tx) * 4];
            const ulonglong2* wp1 = (const ulonglong2*)&Ws2[(((k >> 2) * 64) + tx + 32) * 4];
            ulonglong2 wa0 = wp0[0], wb0 = wp0[1];
            ulonglong2 wa1 = wp1[0], wb1 = wp1[1];
            #pragma unroll
            for (int r = 0; r < 4; r++) {
                const ulonglong2* xp = (const ulonglong2*)&Xs2[(tg * 4 + r) * 64 + k];
                ulonglong2 xa = xp[0], xb = xp[1];
                acc[0][r] = ffma2(xa.x, wa0.x, acc[0][r]);
                acc[0][r] = ffma2(xa.y, wa0.y, acc[0][r]);
                acc[0][r] = ffma2(xb.x, wb0.x, acc[0][r]);
                acc[0][r] = ffma2(xb.y, wb0.y, acc[0][r]);
                acc[1][r] = ffma2(xa.x, wa1.x, acc[1][r]);
                acc[1][r] = ffma2(xa.y, wa1.y, acc[1][r]);
                acc[1][r] = ffma2(xb.x, wb1.x, acc[1][r]);
                acc[1][r] = ffma2(xb.y, wb1.y, acc[1][r]);
            }
        }
        __syncthreads();
    }

    #pragma unroll
    for (int r = 0; r < 4; r++) {
        int row = row0 + tg * 4 + r;
        float di = g_dinv[row];
        float di2 = di * di;
        #pragma unroll
        for (int c = 0; c < 2; c++) {
            int cp = tx + c * 32;                  // float2 column index
            float2 a = unpack2(acc[c][r]);
            ((float2*)g_h1)[(size_t)row * 64 + cp] = a;
            float2 bv = ((const float2*)b1)[cp];
            float2 o = make_float2(bv.x + a.x * di2, bv.y + a.y * di2);
            ((float2*)g_agg1)[(size_t)row * 64 + cp] = o;
        }
    }
}

// ---------------- layer-1 edge scatter: warp per edge ------------------------
__global__ void k_scat1(const void* __restrict__ ei, int E) {
    int w = (blockIdx.x * blockDim.x + threadIdx.x) >> 5;
    int lane = threadIdx.x & 31;
    if (w < E) {
        int is64 = g_is64;
        int s = eidx(ei, w, is64);
        int d = eidx(ei, (long long)E + w, is64);
        float nm = g_dinv[s] * g_dinv[d];
        const float4* hp = (const float4*)(g_h1 + (size_t)s * FH);
        float4 v = hp[lane];
        red_add_v4(g_agg1 + (size_t)d * FH + lane * 4,
                   v.x * nm, v.y * nm, v.z * nm, v.w * nm);
    }
}

// ---------------- GEMM2: relu(agg1)[100000x128] @ W2[128x40], packed --------
// 160 thr: tx=t%20 colpair, tg=t/20 rows tg*4..+3. 32 rows/blk. ReLU fused on load.
// Epilogue fuses: h2 = acc ; agg2 = b2 + acc*dinv^2.
__global__ void __launch_bounds__(160) k_gemm2(const float* __restrict__ W2,
                                               const float* __restrict__ b2) {
    __shared__ u64 Ws2[32 * 20 * 4];  // [(k>>2)*20 + cp]*4 + (k&3)  (20 KB)
    __shared__ u64 Xs2[32 * 128];     // [row][k] duplicated          (32 KB)
    int t = threadIdx.x;
    int tx = t % 20, tg = t / 20;
    int row0 = blockIdx.x * 32;

    const float2* Wg = (const float2*)W2;
    for (int i = t; i < 2560; i += 160) {
        int k = i / 20, cp = i % 20;
        float2 w = Wg[i];
        Ws2[(((k >> 2) * 20) + cp) * 4 + (k & 3)] = pack2(w.x, w.y);
    }
    for (int i = t; i < 4096; i += 160) {
        int r = i >> 7, k = i & 127;
        float v = fmaxf(g_agg1[(size_t)(row0 + r) * FH + k], 0.f);
        Xs2[i] = pack2(v, v);
    }
    __syncthreads();

    u64 acc[4] = {0ULL, 0ULL, 0ULL, 0ULL};
    #pragma unroll
    for (int k = 0; k < 128; k += 4) {
        const ulonglong2* wp = (const ulonglong2*)&Ws2[(((k >> 2) * 20) + tx) * 4];
        ulonglong2 wa = wp[0], wb = wp[1];
        #pragma unroll
        for (int r = 0; r < 4; r++) {
            const ulonglong2* xp = (const ulonglong2*)&Xs2[(tg * 4 + r) * 128 + k];
            ulonglong2 xa = xp[0], xb = xp[1];
            acc[r] = ffma2(xa.x, wa.x, acc[r]);
            acc[r] = ffma2(xa.y, wa.y, acc[r]);
            acc[r] = ffma2(xb.x, wb.x, acc[r]);
            acc[r] = ffma2(xb.y, wb.y, acc[r]);
        }
    }

    #pragma unroll
    for (int r = 0; r < 4; r++) {
        int row = row0 + tg * 4 + r;
        float di = g_dinv[row];
        float di2 = di * di;
        float2 a = unpack2(acc[r]);
        ((float2*)g_h2)[(size_t)row * 20 + tx] = a;
        float2 bv = ((const float2*)b2)[tx];
        float2 o = make_float2(bv.x + a.x * di2, bv.y + a.y * di2);
        ((float2*)g_agg2)[(size_t)row * 20 + tx] = o;
    }
}

// ---------------- layer-2 edge scatter: thread per (edge, f4 chunk) ----------
__global__ void k_scat2(const void* __restrict__ ei, int E) {
    long long idx = (long long)blockIdx.x * blockDim.x + threadIdx.x;
    if (idx < (long long)E * 10) {
        int e = (int)(idx / 10);
        int q = (int)(idx - (long long)e * 10);
        int is64 = g_is64;
        int s = eidx(ei, e, is64);
        int d = eidx(ei, (long long)E + e, is64);
        float nm = g_dinv[s] * g_dinv[d];
        const float4* hp = (const float4*)(g_h2 + (size_t)s * FO);
        float4 v = hp[q];
        red_add_v4(g_agg2 + (size_t)d * FO + q * 4,
                   v.x * nm, v.y * nm, v.z * nm, v.w * nm);
    }
}

// ---------------- log_softmax, warp per row ----------------------------------
__global__ void k_lsm(float* __restrict__ out) {
    int row = (blockIdx.x * blockDim.x + threadIdx.x) >> 5;
    int lane = threadIdx.x & 31;
    if (row < NN) {
        const float* in = g_agg2 + (size_t)row * FO;
        float v0 = in[lane];
        float v1 = (lane < 8) ? in[32 + lane] : -CUDART_INF_F;
        float m = fmaxf(v0, v1);
        #pragma unroll
        for (int o = 16; o; o >>= 1) m = fmaxf(m, __shfl_xor_sync(0xffffffffu, m, o));
        float s = expf(v0 - m) + ((lane < 8) ? expf(v1 - m) : 0.f);
        #pragma unroll
        for (int o = 16; o; o >>= 1) s += __shfl_xor_sync(0xffffffffu, s, o);
        float ls = m + logf(s);
        out[(size_t)row * FO + lane] = v0 - ls;
        if (lane < 8) out[(size_t)row * FO + 32 + lane] = v1 - ls;
    }
}

// ---------------- launch ------------------------------------------------------
extern "C" void kernel_launch(void* const* d_in, const int* in_sizes, int n_in,
                              void* d_out, int out_size) {
    const float* x  = (const float*)d_in[0];
    const void*  ei = d_in[1];
    const float* W1 = (const float*)d_in[2];
    const float* b1 = (const float*)d_in[3];
    const float* W2 = (const float*)d_in[4];
    const float* b2 = (const float*)d_in[5];
    float* out = (float*)d_out;
    int E = in_sizes[1] / 2;

    k_detect<<<1, 32>>>(ei);
    k_deg_init<<<(NN + 255) / 256, 256>>>();
    k_deg_count<<<(E + 255) / 256, 256>>>(ei, E);
    k_dinv<<<(NN + 255) / 256, 256>>>();

    k_gemm1<<<NN / 32, 256>>>(x, W1, b1);       // 3125 blocks, also inits agg1
    k_scat1<<<(E + 7) / 8, 256>>>(ei, E);

    k_gemm2<<<NN / 32, 160>>>(W2, b2);          // relu fused, also inits agg2
    long long tot2 = (long long)E * 10;
    k_scat2<<<(unsigned)((tot2 + 255) / 256), 256>>>(ei, E);

    k_lsm<<<(NN + 7) / 8, 256>>>(out);
}

// round 4
// speedup vs baseline: 1.2794x; 1.2794x over previous
#include <cuda_runtime.h>
#include <math_constants.h>

#define NN 100000
#define FI 256
#define FH 128
#define FO 40

typedef unsigned long long u64;

// ---------------- scratch (static device globals) ---------------------------
__device__ __align__(256) float g_deg[NN];
__device__ __align__(256) float g_dinv[NN];
__device__ __align__(256) float g_h1[NN * FH];    // x @ W1
__device__ __align__(256) float g_agg1[NN * FH];  // b1 + self + edge aggregate
__device__ __align__(256) float g_h2[NN * FO];    // relu(agg1) @ W2
__device__ __align__(256) float g_agg2[NN * FO];  // b2 + self + edge aggregate
__device__ int g_is64;

// ---------------- packed fp32x2 helpers -------------------------------------
__device__ __forceinline__ u64 pack2(float lo, float hi) {
    u64 r; asm("mov.b64 %0, {%1, %2};" : "=l"(r) : "f"(lo), "f"(hi)); return r;
}
__device__ __forceinline__ float2 unpack2(u64 v) {
    float2 f; asm("mov.b64 {%0, %1}, %2;" : "=f"(f.x), "=f"(f.y) : "l"(v)); return f;
}
__device__ __forceinline__ u64 ffma2(u64 a, u64 b, u64 c) {
    u64 d; asm("fma.rn.f32x2 %0, %1, %2, %3;" : "=l"(d) : "l"(a), "l"(b), "l"(c)); return d;
}
__device__ __forceinline__ void red_add_v4(float* p, float a, float b, float c, float d) {
    asm volatile("red.global.add.v4.f32 [%0], {%1,%2,%3,%4};"
                 :: "l"(p), "f"(a), "f"(b), "f"(c), "f"(d) : "memory");
}
__device__ __forceinline__ int eidx(const void* p, long long i, int is64) {
    if (is64) return (int)((const long long*)p)[i];
    return ((const int*)p)[i];
}

// ---------------- prep: dtype probe + degree init (fused) --------------------
__global__ void k_prep(const void* ei) {
    int i = blockIdx.x * blockDim.x + threadIdx.x;
    if (i < NN) g_deg[i] = 1.0f;                  // self loop
    if (i == 0) {
        const long long* p = (const long long*)ei;
        int ok = 1;
        #pragma unroll
        for (int j = 0; j < 32; j++) {
            long long v = p[j];
            if (v < 0 || v >= NN) ok = 0;
        }
        g_is64 = ok;                              // int32 data ~never passes
    }
}

__global__ void k_deg_count(const void* ei, int E) {
    int i = blockIdx.x * blockDim.x + threadIdx.x;
    if (i < E) {
        int d = eidx(ei, (long long)E + i, g_is64);
        atomicAdd(&g_deg[d], 1.0f);
    }
}

__global__ void k_dinv() {
    int i = blockIdx.x * blockDim.x + threadIdx.x;
    if (i < NN) g_dinv[i] = rsqrtf(fmaxf(g_deg[i], 1.0f));
}

// ---------------- GEMM1: 100000x256 @ 256x128, packed f32x2 -----------------
// 256 thr = 8 warps. Warp tg owns rows tg*8..tg*8+7 (64 rows/block).
// Lane tx owns colpairs {tx, tx+32} (=> cols 2tx,2tx+1, 2tx+64, 2tx+65).
// K chunked by 32. Ws2[k][cp] (lane-consecutive 8B => conflict-free LDS.64);
// Xs2[r][k] duplicated-pack, warp-uniform broadcast reads.
// Epilogue fuses: h1 = acc ; agg1 = b1 + acc*dinv^2 (self-loop init).
__global__ void __launch_bounds__(256) k_gemm1(const float* __restrict__ x,
                                               const float* __restrict__ W1,
                                               const float* __restrict__ b1) {
    __shared__ u64 Ws2[32 * 64];  // [k][cp]          16 KB
    __shared__ u64 Xs2[64 * 32];  // [r][k] dup-pack  16 KB
    int t = threadIdx.x;
    int tx = t & 31, tg = t >> 5;
    int row0 = blockIdx.x * 64;

    u64 acc[2][8];
    #pragma unroll
    for (int c = 0; c < 2; c++)
        #pragma unroll
        for (int r = 0; r < 8; r++) acc[c][r] = 0ULL;

    for (int kt = 0; kt < 8; kt++) {
        const float2* Wg = (const float2*)(W1 + (size_t)(kt * 32) * 128);
        #pragma unroll
        for (int i = t; i < 2048; i += 256) {
            float2 w = Wg[i];              // i = k*64 + cp, same layout as smem
            Ws2[i] = pack2(w.x, w.y);
        }
        #pragma unroll
        for (int i = t; i < 2048; i += 256) {
            int r = i >> 5, k = i & 31;
            int row = row0 + r; if (row >= NN) row = NN - 1;
            float v = x[(size_t)row * FI + kt * 32 + k];
            Xs2[i] = pack2(v, v);
        }
        __syncthreads();

        #pragma unroll
        for (int k = 0; k < 32; k += 2) {
            u64 w00 = Ws2[k * 64 + tx];
            u64 w01 = Ws2[k * 64 + tx + 32];
            u64 w10 = Ws2[(k + 1) * 64 + tx];
            u64 w11 = Ws2[(k + 1) * 64 + tx + 32];
            #pragma unroll
            for (int r = 0; r < 8; r++) {
                ulonglong2 xv = *(const ulonglong2*)&Xs2[(tg * 8 + r) * 32 + k];
                acc[0][r] = ffma2(xv.x, w00, acc[0][r]);
                acc[1][r] = ffma2(xv.x, w01, acc[1][r]);
                acc[0][r] = ffma2(xv.y, w10, acc[0][r]);
                acc[1][r] = ffma2(xv.y, w11, acc[1][r]);
            }
        }
        __syncthreads();
    }

    #pragma unroll
    for (int r = 0; r < 8; r++) {
        int row = row0 + tg * 8 + r;
        if (row < NN) {
            float di = g_dinv[row];
            float di2 = di * di;
            #pragma unroll
            for (int c = 0; c < 2; c++) {
                int cp = tx + c * 32;
                float2 a = unpack2(acc[c][r]);
                ((float2*)g_h1)[(size_t)row * 64 + cp] = a;
                float2 bv = ((const float2*)b1)[cp];
                float2 o = make_float2(bv.x + a.x * di2, bv.y + a.y * di2);
                ((float2*)g_agg1)[(size_t)row * 64 + cp] = o;
            }
        }
    }
}

// ---------------- layer-1 edge scatter: warp per edge ------------------------
__global__ void k_scat1(const void* __restrict__ ei, int E) {
    int w = (blockIdx.x * blockDim.x + threadIdx.x) >> 5;
    int lane = threadIdx.x & 31;
    if (w < E) {
        int is64 = g_is64;
        int s = eidx(ei, w, is64);
        int d = eidx(ei, (long long)E + w, is64);
        float nm = g_dinv[s] * g_dinv[d];
        const float4* hp = (const float4*)(g_h1 + (size_t)s * FH);
        float4 v = hp[lane];
        red_add_v4(g_agg1 + (size_t)d * FH + lane * 4,
                   v.x * nm, v.y * nm, v.z * nm, v.w * nm);
    }
}

// ---------------- GEMM2: relu(agg1)[100000x128] @ W2[128x40] ----------------
// 160 thr: tx=t%20 (colpair), tg=t/20 (0..7) -> rows tg*4..+3 (32 rows/block).
// K chunked by 64. Ws2[k][cp] conflict-free; Xs2[r][k] dup-pack (<=2 rows/warp).
// ReLU fused on X load. Epilogue fuses: h2 = acc ; agg2 = b2 + acc*dinv^2.
__global__ void __launch_bounds__(160) k_gemm2(const float* __restrict__ W2,
                                               const float* __restrict__ b2) {
    __shared__ u64 Ws2[64 * 20];  // [k][cp]          10 KB
    __shared__ u64 Xs2[32 * 64];  // [r][k] dup-pack  16 KB
    int t = threadIdx.x;
    int tx = t % 20, tg = t / 20;
    int row0 = blockIdx.x * 32;

    u64 acc[4] = {0ULL, 0ULL, 0ULL, 0ULL};

    for (int kt = 0; kt < 2; kt++) {
        const float2* Wg = (const float2*)(W2 + (size_t)(kt * 64) * 40);
        for (int i = t; i < 1280; i += 160) {
            float2 w = Wg[i];              // i = k*20 + cp
            Ws2[i] = pack2(w.x, w.y);
        }
        for (int i = t; i < 2048; i += 160) {
            int r = i >> 6, k = i & 63;
            float v = fmaxf(g_agg1[(size_t)(row0 + r) * FH + kt * 64 + k], 0.f);
            Xs2[i] = pack2(v, v);
        }
        __syncthreads();

        #pragma unroll
        for (int k = 0; k < 64; k += 2) {
            u64 w0 = Ws2[k * 20 + tx];
            u64 w1 = Ws2[(k + 1) * 20 + tx];
            #pragma unroll
            for (int r = 0; r < 4; r++) {
                ulonglong2 xv = *(const ulonglong2*)&Xs2[(tg * 4 + r) * 64 + k];
                acc[r] = ffma2(xv.x, w0, acc[r]);
                acc[r] = ffma2(xv.y, w1, acc[r]);
            }
        }
        __syncthreads();
    }

    #pragma unroll
    for (int r = 0; r < 4; r++) {
        int row = row0 + tg * 4 + r;
        float di = g_dinv[row];
        float di2 = di * di;
        float2 a = unpack2(acc[r]);
        ((float2*)g_h2)[(size_t)row * 20 + tx] = a;
        float2 bv = ((const float2*)b2)[tx];
        float2 o = make_float2(bv.x + a.x * di2, bv.y + a.y * di2);
        ((float2*)g_agg2)[(size_t)row * 20 + tx] = o;
    }
}

// ---------------- layer-2 edge scatter: thread per (edge, f4 chunk) ----------
__global__ void k_scat2(const void* __restrict__ ei, int E) {
    long long idx = (long long)blockIdx.x * blockDim.x + threadIdx.x;
    if (idx < (long long)E * 10) {
        int e = (int)(idx / 10);
        int q = (int)(idx - (long long)e * 10);
        int is64 = g_is64;
        int s = eidx(ei, e, is64);
        int d = eidx(ei, (long long)E + e, is64);
        float nm = g_dinv[s] * g_dinv[d];
        const float4* hp = (const float4*)(g_h2 + (size_t)s * FO);
        float4 v = hp[q];
        red_add_v4(g_agg2 + (size_t)d * FO + q * 4,
                   v.x * nm, v.y * nm, v.z * nm, v.w * nm);
    }
}

// ---------------- log_softmax, warp per row ----------------------------------
__global__ void k_lsm(float* __restrict__ out) {
    int row = (blockIdx.x * blockDim.x + threadIdx.x) >> 5;
    int lane = threadIdx.x & 31;
    if (row < NN) {
        const float* in = g_agg2 + (size_t)row * FO;
        float v0 = in[lane];
        float v1 = (lane < 8) ? in[32 + lane] : -CUDART_INF_F;
        float m = fmaxf(v0, v1);
        #pragma unroll
        for (int o = 16; o; o >>= 1) m = fmaxf(m, __shfl_xor_sync(0xffffffffu, m, o));
        float s = expf(v0 - m) + ((lane < 8) ? expf(v1 - m) : 0.f);
        #pragma unroll
        for (int o = 16; o; o >>= 1) s += __shfl_xor_sync(0xffffffffu, s, o);
        float ls = m + logf(s);
        out[(size_t)row * FO + lane] = v0 - ls;
        if (lane < 8) out[(size_t)row * FO + 32 + lane] = v1 - ls;
    }
}

// ---------------- launch ------------------------------------------------------
extern "C" void kernel_launch(void* const* d_in, const int* in_sizes, int n_in,
                              void* d_out, int out_size) {
    const float* x  = (const float*)d_in[0];
    const void*  ei = d_in[1];
    const float* W1 = (const float*)d_in[2];
    const float* b1 = (const float*)d_in[3];
    const float* W2 = (const float*)d_in[4];
    const float* b2 = (const float*)d_in[5];
    float* out = (float*)d_out;
    int E = in_sizes[1] / 2;

    k_prep<<<(NN + 255) / 256, 256>>>(ei);            // 0: detect + deg init
    k_deg_count<<<(E + 255) / 256, 256>>>(ei, E);     // 1
    k_dinv<<<(NN + 255) / 256, 256>>>();              // 2

    k_gemm1<<<(NN + 63) / 64, 256>>>(x, W1, b1);      // 3: also inits agg1
    k_scat1<<<(E + 7) / 8, 256>>>(ei, E);             // 4

    k_gemm2<<<NN / 32, 160>>>(W2, b2);                // 5: relu fused, inits agg2
    long long tot2 = (long long)E * 10;
    k_scat2<<<(unsigned)((tot2 + 255) / 256), 256>>>(ei, E);  // 6

    k_lsm<<<(NN + 7) / 8, 256>>>(out);                // 7
}